// round 14
// baseline (speedup 1.0000x reference)
#include <cuda_runtime.h>
#include <cstdint>

#define NN     256
#define BB     8
#define SS     14
#define BS     (BB*SS)
#define NDAT   12      // S - len(PILOTS)

#define NSM      148
#define UNIT_ROWS 32
#define NUNITS   (BS * (NN / UNIT_ROWS))   // 112*8 = 896

__device__ float4   g_h4[BS * NN / 2];     // h as float4 pairs (re,im,re,im)
__device__ int      g_idx[BS];
__device__ unsigned g_ctr;

// ---------------------------------------------------------------------------
// Kernel 1: per-(b,s) 256-pt DFT (radix-16 x radix-16) * conj(zc) -> g_h4;
// resolves cov index; resets work counter.
// ---------------------------------------------------------------------------
__global__ void __launch_bounds__(NN)
prep_kernel(const float* __restrict__ xr,
            const float* __restrict__ xi,
            const float* __restrict__ zr,
            const float* __restrict__ zi,
            const int*   __restrict__ shift,
            const int*   __restrict__ gidx)
{
    __shared__ float2 xs[16 * 17];
    __shared__ float2 aa[17 * 16];
    __shared__ float2 w16[16];

    const int bs  = blockIdx.x;
    const int b   = bs / SS;
    const int s   = bs % SS;
    const int tid = threadIdx.x;

    if (tid == 0) {
        const int g = gidx[s];
        g_idx[bs]   = (g == 0) ? 0 : shift[b * NDAT + g - 1];
        if (bs == 0) g_ctr = 0;          // reset work-steal counter each launch
    }

    xs[(tid & 15) * 17 + (tid >> 4)] = make_float2(xr[bs * NN + tid],
                                                   xi[bs * NN + tid]);
    if (tid < 16) {
        float sn, cs;
        sincospif(-(float)tid * 0.125f, &sn, &cs);       // e^{-2pi i t/16}
        w16[tid] = make_float2(cs, sn);
    }
    __syncthreads();

    {   // stage A
        const int k0 = tid >> 4, n0 = tid & 15;
        float ar = 0.0f, ai = 0.0f;
#pragma unroll
        for (int n1 = 0; n1 < 16; n1++) {
            const float2 v  = xs[n0 * 17 + n1];
            const float2 ww = w16[(k0 * n1) & 15];
            ar = fmaf(v.x, ww.x, fmaf(-v.y, ww.y, ar));
            ai = fmaf(v.x, ww.y, fmaf( v.y, ww.x, ai));
        }
        float sn, cs;
        sincospif(-(float)(k0 * n0) * (1.0f / 128.0f), &sn, &cs);
        aa[n0 * 17 + k0] = make_float2(ar * cs - ai * sn, ar * sn + ai * cs);
    }
    __syncthreads();

    {   // stage B + conj(zc)
        const int k0 = tid & 15, k1 = tid >> 4;
        float Xr = 0.0f, Xi = 0.0f;
#pragma unroll
        for (int n0 = 0; n0 < 16; n0++) {
            const float2 v  = aa[n0 * 17 + k0];
            const float2 ww = w16[(k1 * n0) & 15];
            Xr = fmaf(v.x, ww.x, fmaf(-v.y, ww.y, Xr));
            Xi = fmaf(v.x, ww.y, fmaf( v.y, ww.x, Xi));
        }
        const float a  = zr[tid];
        const float bq = -zi[tid];
        ((float2*)g_h4)[bs * NN + tid] =
            make_float2(Xr * a - Xi * bq, Xr * bq + Xi * a);
    }
}

// ---------------------------------------------------------------------------
// Kernel 2: persistent work-stealing matvec.
// Grid = 148 blocks x 512 threads (one per SM). Units = 896 x (bs, 32 rows).
// Per unit: 16 warps x 2 rows, full 8xLDG.128 prefetch per warp, h from
// L2-hot g_h4, two interleaved shuffle reductions, STG.64 per warp.
// ---------------------------------------------------------------------------
__global__ void __launch_bounds__(512)
matvec_ws(const float* __restrict__ cr,
          const float* __restrict__ ci,
          float*       __restrict__ out)
{
    __shared__ unsigned s_u;

    const int tid  = threadIdx.x;
    const int w    = tid >> 5;
    const int lane = tid & 31;

    for (;;) {
        __syncthreads();                       // protect s_u from prior read
        if (tid == 0) s_u = atomicAdd(&g_ctr, 1u);
        __syncthreads();
        const unsigned u = s_u;
        if (u >= NUNITS) return;

        const int bs      = u >> 3;
        const int rowBase = (u & 7) * UNIT_ROWS;
        const int idx     = g_idx[bs];                 // L2-hot
        const size_t base = (size_t)idx * NN * NN;

        const int r0 = rowBase + w * 2;                // this warp's 2 rows

        // full prefetch: 2 rows x (cr + ci) x 2 float4 = 8 LDG.128
        const float4* crp0 = (const float4*)(cr + base + (size_t)r0 * NN) + lane * 2;
        const float4* cip0 = (const float4*)(ci + base + (size_t)r0 * NN) + lane * 2;
        const float4* crp1 = crp0 + 64;                // next row = +256 floats
        const float4* cip1 = cip0 + 64;

        const float4 A00 = crp0[0], A01 = crp0[1];
        const float4 C00 = cip0[0], C01 = cip0[1];
        const float4 A10 = crp1[0], A11 = crp1[1];
        const float4 C10 = cip1[0], C11 = cip1[1];

        // h for m = lane*8 .. lane*8+7 (4 float4 = 8 complex), L2-hot
        const float4* hp = g_h4 + bs * (NN / 2) + lane * 4;
        const float4 h0 = hp[0], h1 = hp[1], h2 = hp[2], h3 = hp[3];

        float re0 = 0.0f, re1 = 0.0f;
        re0 = fmaf(A00.x, h0.x, fmaf(-C00.x, h0.y, re0));
        re1 = fmaf(A10.x, h0.x, fmaf(-C10.x, h0.y, re1));
        re0 = fmaf(A00.y, h0.z, fmaf(-C00.y, h0.w, re0));
        re1 = fmaf(A10.y, h0.z, fmaf(-C10.y, h0.w, re1));
        re0 = fmaf(A00.z, h1.x, fmaf(-C00.z, h1.y, re0));
        re1 = fmaf(A10.z, h1.x, fmaf(-C10.z, h1.y, re1));
        re0 = fmaf(A00.w, h1.z, fmaf(-C00.w, h1.w, re0));
        re1 = fmaf(A10.w, h1.z, fmaf(-C10.w, h1.w, re1));
        re0 = fmaf(A01.x, h2.x, fmaf(-C01.x, h2.y, re0));
        re1 = fmaf(A11.x, h2.x, fmaf(-C11.x, h2.y, re1));
        re0 = fmaf(A01.y, h2.z, fmaf(-C01.y, h2.w, re0));
        re1 = fmaf(A11.y, h2.z, fmaf(-C11.y, h2.w, re1));
        re0 = fmaf(A01.z, h3.x, fmaf(-C01.z, h3.y, re0));
        re1 = fmaf(A11.z, h3.x, fmaf(-C11.z, h3.y, re1));
        re0 = fmaf(A01.w, h3.z, fmaf(-C01.w, h3.w, re0));
        re1 = fmaf(A11.w, h3.z, fmaf(-C11.w, h3.w, re1));

        // two independent reductions, interleaved
#pragma unroll
        for (int o = 16; o > 0; o >>= 1) {
            re0 += __shfl_xor_sync(0xffffffffu, re0, o);
            re1 += __shfl_xor_sync(0xffffffffu, re1, o);
        }

        if (lane == 0)
            *(float2*)(out + bs * NN + r0) = make_float2(re0, re1);
    }
}

extern "C" void kernel_launch(void* const* d_in, const int* in_sizes, int n_in,
                              void* d_out, int out_size)
{
    const float* xr    = (const float*)d_in[0];
    const float* xi    = (const float*)d_in[1];
    const float* cr    = (const float*)d_in[2];
    const float* ci    = (const float*)d_in[3];
    const float* zr    = (const float*)d_in[4];
    const float* zi    = (const float*)d_in[5];
    const int*   shift = (const int*)d_in[6];
    const int*   gidx  = (const int*)d_in[7];

    prep_kernel<<<BS, NN>>>(xr, xi, zr, zi, shift, gidx);
    matvec_ws<<<NSM, 512>>>(cr, ci, (float*)d_out);
}